// round 13
// baseline (speedup 1.0000x reference)
#include <cuda_runtime.h>
#include <cuda_fp16.h>
#include <cstdint>

typedef unsigned long long ull;

#define B_N 2048

// ---------------- device scratch (zero-init at load; pad cells never written) ----
__device__ __half g_in0h[2 * 65 * 16 * 2048];                // conv1 input fp16, padded CHWN
__device__ __half g_zeroH[256];                              // stays zero
__device__ __half g_a1[(size_t)64 * 34 * 16 * 2048];         // conv1 out (fp16)
__device__ __half g_a2[(size_t)128 * 18 * 16 * 2048];        // conv2 out (fp16)
__device__ __half g_w1p[64 * 32];                            // conv1 weights, K padded 18->32
__device__ __half g_w2[128 * 576];
__device__ __half g_w3[256 * 1152];

// ---------------- helpers ----------------
__device__ __forceinline__ uint32_t smem_u32(const void* p) {
    uint32_t a;
    asm("{ .reg .u64 t; cvta.to.shared.u64 t, %1; cvt.u32.u64 %0, t; }"
        : "=r"(a) : "l"(p));
    return a;
}
__device__ __forceinline__ uint32_t f16x2(float y0, float y1) {
    __half2 h = __floats2half2_rn(y0, y1);      // y0 -> low half
    return *reinterpret_cast<uint32_t*>(&h);
}

// ldmatrix / mma.sync (base ISA)
__device__ __forceinline__ void ldsm4(uint32_t* r, uint32_t a) {
    asm volatile("ldmatrix.sync.aligned.m8n8.x4.shared.b16 {%0,%1,%2,%3}, [%4];"
        : "=r"(r[0]), "=r"(r[1]), "=r"(r[2]), "=r"(r[3]) : "r"(a));
}
__device__ __forceinline__ void ldsm4t(uint32_t* r, uint32_t a) {
    asm volatile("ldmatrix.sync.aligned.m8n8.x4.trans.shared.b16 {%0,%1,%2,%3}, [%4];"
        : "=r"(r[0]), "=r"(r[1]), "=r"(r[2]), "=r"(r[3]) : "r"(a));
}
__device__ __forceinline__ void mma16816(float* d, const uint32_t* a, const uint32_t* b) {
    asm volatile(
        "mma.sync.aligned.m16n8k16.row.col.f32.f16.f16.f32 "
        "{%0,%1,%2,%3}, {%4,%5,%6,%7}, {%8,%9}, {%0,%1,%2,%3};"
        : "+f"(d[0]), "+f"(d[1]), "+f"(d[2]), "+f"(d[3])
        : "r"(a[0]), "r"(a[1]), "r"(a[2]), "r"(a[3]), "r"(b[0]), "r"(b[1]));
}

// cp.async
#define CP_ASYNC16(dst, src) \
    asm volatile("cp.async.cg.shared.global [%0], [%1], 16;" :: "r"(dst), "l"(src))
#define CP_COMMIT() asm volatile("cp.async.commit_group;" ::: "memory")
#define CP_WAIT0()  asm volatile("cp.async.wait_group 0;" ::: "memory")
#define CP_WAIT1()  asm volatile("cp.async.wait_group 1;" ::: "memory")

// ======================= small prep kernels =======================
__global__ void zero_out_kernel(float* p, int n) {
    int i = blockIdx.x * 1024 + threadIdx.x;
    if (i < n) p[i] = 0.f;
}

// x,sigmas [B][64][14] -> g_in0h [2][65][16][B] fp16
__global__ void prep_input_kernel(const float* __restrict__ x,
                                  const float* __restrict__ sig) {
    int fk = blockIdx.x;            // 0..895
    int f = fk / 14, k = fk % 14;
    int t = threadIdx.x;
    for (int it = 0; it < 8; it++) {
        int b = it * 256 + t;
        float xv = x[(size_t)b * 896 + fk];
        float sv = sig[(size_t)b * 896 + fk] * 10.0f;
        g_in0h[((size_t)(0 * 65 + f + 1) * 16 + k + 1) * B_N + b] = __float2half_rn(xv);
        g_in0h[((size_t)(1 * 65 + f + 1) * 16 + k + 1) * B_N + b] = __float2half_rn(sv);
    }
}

// fp32 weights -> fp16 (single limb)
__global__ void cvt_w_kernel(const float* __restrict__ w, __half* __restrict__ o, int n) {
    int i = blockIdx.x * 256 + threadIdx.x;
    if (i >= n) return;
    o[i] = __float2half_rn(w[i]);
}

// conv1 weights [64][2][3][3] -> [64co][32k] fp16, zeros for k>=18
__global__ void cvt_w1_kernel(const float* __restrict__ w1) {
    int i = blockIdx.x * 256 + threadIdx.x;
    if (i >= 2048) return;
    int co = i >> 5, k = i & 31;
    g_w1p[i] = (k < 18) ? __float2half_rn(w1[co * 18 + k]) : __half(0.f);
}

// ======================= conv1 via mma (64co x 256n, K=32 single chunk) ======
// 256 threads, 8 warps as 2m x 4n (warp = 32co x 64n).
// smem: A [64][40h] pitch 80B @0 (5120B), B [32][264h] pitch 528B @5120 (16896B).
__global__ void __launch_bounds__(256, 2)
conv1_mma(const float* __restrict__ g1, const float* __restrict__ b1,
          const float* __restrict__ m1, const float* __restrict__ v1)
{
    __shared__ __align__(16) char smem[22016];
    const uint32_t smb = smem_u32(smem);
    const int OFF_B = 5120;

    const int tid  = threadIdx.x;
    const int lane = tid & 31, wid = tid >> 5;
    const int wm = wid & 1, wn = wid >> 1;          // 2m x 4n warps
    const int g = lane >> 2, t = lane & 3;
    const int h  = blockIdx.x;                      // 0..31
    const int n0 = blockIdx.y * 256;
    const int w_pos = n0 >> 11;
    const int b0    = n0 & 2047;

    // stage A (64 rows x 64B)
    {
        int row = tid >> 2, q = tid & 3;
        CP_ASYNC16(smb + (uint32_t)(row * 80 + q * 16), g_w1p + row * 32 + q * 8);
    }
    // stage B (32 rows x 512B)
    #pragma unroll
    for (int it = 0; it < 4; it++) {
        int e = it * 256 + tid;                     // 0..1023
        int row = e >> 5, n16 = e & 31;
        int ci = row / 9;
        int r9 = row - ci * 9;
        int kh = r9 / 3;
        int kw = r9 - kh * 3;
        const __half* src = (row < 18)
            ? g_in0h + ((size_t)(ci * 65 + 2 * h + kh) * 16 + w_pos + kw) * B_N
                     + b0 + n16 * 8
            : g_zeroH + n16 * 8 % 256;
        CP_ASYNC16(smb + (uint32_t)(OFF_B + row * 528 + n16 * 16), src);
    }
    CP_COMMIT();
    CP_WAIT0();
    __syncthreads();

    const int rA = lane & 15;
    const int kA = (lane >> 4) << 3;
    const uint32_t aA0 = smb + (uint32_t)((wm * 32 +  0 + rA) * 80 + kA * 2);
    const uint32_t aA1 = smb + (uint32_t)((wm * 32 + 16 + rA) * 80 + kA * 2);
    const uint32_t bA  = smb + (uint32_t)(OFF_B + (lane & 15) * 528
                                          + (lane >> 4) * 16 + wn * 128);

    float acc[2][8][4];
    #pragma unroll
    for (int mt = 0; mt < 2; mt++)
        #pragma unroll
        for (int nt = 0; nt < 8; nt++)
            #pragma unroll
            for (int i = 0; i < 4; i++) acc[mt][nt][i] = 0.f;

    #pragma unroll
    for (int ks = 0; ks < 2; ks++) {
        uint32_t Ah0[4], Ah1[4];
        ldsm4(Ah0, aA0 + ks * 32);
        ldsm4(Ah1, aA1 + ks * 32);
        #pragma unroll
        for (int ntp = 0; ntp < 4; ntp++) {
            uint32_t bf[4];
            ldsm4t(bf, bA + ks * (16 * 528) + ntp * 32);
            mma16816(acc[0][2 * ntp],     Ah0, bf);
            mma16816(acc[1][2 * ntp],     Ah1, bf);
            mma16816(acc[0][2 * ntp + 1], Ah0, bf + 2);
            mma16816(acc[1][2 * ntp + 1], Ah1, bf + 2);
        }
    }

    // epilogue: BN + ReLU -> g_a1 [64][34][16][B]
    #pragma unroll
    for (int mt = 0; mt < 2; mt++) {
        int co0 = wm * 32 + mt * 16 + g, co1 = co0 + 8;
        float sc0 = g1[co0] * rsqrtf(v1[co0] + 1e-5f);
        float sh0 = b1[co0] - m1[co0] * sc0;
        float sc1 = g1[co1] * rsqrtf(v1[co1] + 1e-5f);
        float sh1 = b1[co1] - m1[co1] * sc1;
        size_t base0 = ((size_t)(co0 * 34 + h + 1) * 16 + w_pos + 1) * B_N + b0;
        size_t base1 = ((size_t)(co1 * 34 + h + 1) * 16 + w_pos + 1) * B_N + b0;
        #pragma unroll
        for (int nt = 0; nt < 8; nt++) {
            int nl = wn * 64 + nt * 8 + 2 * t;
            float y0 = fmaxf(fmaf(acc[mt][nt][0], sc0, sh0), 0.f);
            float y1 = fmaxf(fmaf(acc[mt][nt][1], sc0, sh0), 0.f);
            float y2 = fmaxf(fmaf(acc[mt][nt][2], sc1, sh1), 0.f);
            float y3 = fmaxf(fmaf(acc[mt][nt][3], sc1, sh1), 0.f);
            *reinterpret_cast<uint32_t*>(g_a1 + base0 + nl) = f16x2(y0, y1);
            *reinterpret_cast<uint32_t*>(g_a1 + base1 + nl) = f16x2(y2, y3);
        }
    }
}

// ======================= mma.sync conv GEMM v8 (fp16, K-chunk 64) ==========
// CTA: D[128 co][128 n], K-chunk 64, 256 threads (8 warps, 4m x 2n).
// cp.async double-buffered.  MSPLIT: blockIdx.x = h*2 + mtile (L2 pairing).
// Per-buffer: A [128][72h] @0 (pitch 144B), B [64][136h] @18432 (pitch 272B).
static constexpr int OFF_B_L   = 18432;
static constexpr int BUF_SZ    = 35840;
static constexpr int OFF_PART  = 2 * BUF_SZ;        // 256 floats (FUSE4)
static constexpr int SMEM_TOT  = OFF_PART + 1024;   // 72704

template<int HPIN, int CHUNKS, bool FUSE4, bool MSPLIT>
__global__ void __launch_bounds__(256, 2)
conv_mma(const __half* __restrict__ X,
         const __half* __restrict__ W,
         const float* __restrict__ gam, const float* __restrict__ bet,
         const float* __restrict__ mu,  const float* __restrict__ var,
         const float* __restrict__ w4,
         __half* __restrict__ O,
         float* __restrict__ dout, int HP_OUT)
{
    constexpr int KTOT = CHUNKS * 64;
    extern __shared__ __align__(16) char smem[];
    const uint32_t smb = smem_u32(smem);
    float* s_part = reinterpret_cast<float*>(smem + OFF_PART);

    const int tid  = threadIdx.x;
    const int lane = tid & 31, wid = tid >> 5;
    const int wm = wid & 3, wn = wid >> 2;          // 4m x 2n warps
    const int g = lane >> 2, t = lane & 3;
    const int h     = MSPLIT ? (blockIdx.x >> 1) : blockIdx.x;
    const int mtile = MSPLIT ? (blockIdx.x & 1) : 0;
    const int n0 = blockIdx.y * 128;
    const int w_pos = n0 >> 11;
    const int b0    = n0 & 2047;

    if (FUSE4) s_part[tid] = 0.f;

    const int rA = lane & 15;
    const int kA = (lane >> 4) << 3;
    const uint32_t aOff0 = (uint32_t)((wm * 32 +  0 + rA) * 144 + kA * 2);
    const uint32_t aOff1 = (uint32_t)((wm * 32 + 16 + rA) * 144 + kA * 2);
    const uint32_t bOff  = (uint32_t)(OFF_B_L + (lane & 15) * 272
                                      + (lane >> 4) * 16 + wn * 128);

    float acc[2][8][4];
    #pragma unroll
    for (int mt = 0; mt < 2; mt++)
        #pragma unroll
        for (int nt = 0; nt < 8; nt++)
            #pragma unroll
            for (int i = 0; i < 4; i++) acc[mt][nt][i] = 0.f;

    auto stage = [&](int cc, uint32_t bufOff) {
        #pragma unroll
        for (int it = 0; it < 4; it++) {
            int e = it * 256 + tid;                 // 0..1023
            int row = e >> 3, q = e & 7;
            size_t go = (size_t)(mtile * 128 + row) * KTOT + cc * 64 + q * 8;
            uint32_t so = smb + bufOff + (uint32_t)(row * 144 + q * 16);
            CP_ASYNC16(so, W + go);
        }
        #pragma unroll
        for (int it = 0; it < 4; it++) {
            int e = it * 256 + tid;                 // 0..1023
            int row = e >> 4, n16 = e & 15;
            int k = cc * 64 + row;
            int ci = k / 9;
            int r9 = k - ci * 9;
            int kh = r9 / 3;
            int kw = r9 - kh * 3;
            size_t go = ((size_t)(ci * HPIN + 2 * h + kh) * 16 + w_pos + kw) * B_N
                        + b0 + n16 * 8;
            uint32_t so = smb + bufOff + (uint32_t)(OFF_B_L + row * 272 + n16 * 16);
            CP_ASYNC16(so, X + go);
        }
        CP_COMMIT();
    };

    stage(0, 0);

    #pragma unroll 1
    for (int c = 0; c < CHUNKS; c++) {
        const uint32_t cur = (c & 1) ? BUF_SZ : 0;
        if (c + 1 < CHUNKS) {
            stage(c + 1, cur ^ BUF_SZ);
            CP_WAIT1();
        } else {
            CP_WAIT0();
        }
        __syncthreads();

        const uint32_t aHi0 = smb + cur + aOff0;
        const uint32_t aHi1 = smb + cur + aOff1;
        const uint32_t bA   = smb + cur + bOff;
        #pragma unroll
        for (int ks = 0; ks < 4; ks++) {
            uint32_t Ah0[4], Ah1[4];
            ldsm4(Ah0, aHi0 + ks * 32);
            ldsm4(Ah1, aHi1 + ks * 32);
            #pragma unroll
            for (int ntp = 0; ntp < 4; ntp++) {
                uint32_t bf[4];
                ldsm4t(bf, bA + ks * (16 * 272) + ntp * 32);
                mma16816(acc[0][2 * ntp],     Ah0, bf);
                mma16816(acc[1][2 * ntp],     Ah1, bf);
                mma16816(acc[0][2 * ntp + 1], Ah0, bf + 2);
                mma16816(acc[1][2 * ntp + 1], Ah1, bf + 2);
            }
        }
        __syncthreads();
    }

    // ======================= epilogue =======================
    const int co_base = mtile * 128 + wm * 32;
    if (!FUSE4) {
        #pragma unroll
        for (int mt = 0; mt < 2; mt++) {
            int co0 = co_base + mt * 16 + g, co1 = co0 + 8;
            float sc0 = gam[co0] * rsqrtf(var[co0] + 1e-5f);
            float sh0 = bet[co0] - mu[co0] * sc0;
            float sc1 = gam[co1] * rsqrtf(var[co1] + 1e-5f);
            float sh1 = bet[co1] - mu[co1] * sc1;
            size_t base0 = ((size_t)(co0 * HP_OUT + h + 1) * 16 + w_pos + 1) * B_N + b0;
            size_t base1 = ((size_t)(co1 * HP_OUT + h + 1) * 16 + w_pos + 1) * B_N + b0;
            #pragma unroll
            for (int nt = 0; nt < 8; nt++) {
                int nl = wn * 64 + nt * 8 + 2 * t;
                float y0 = fmaxf(fmaf(acc[mt][nt][0], sc0, sh0), 0.f);
                float y1 = fmaxf(fmaf(acc[mt][nt][1], sc0, sh0), 0.f);
                float y2 = fmaxf(fmaf(acc[mt][nt][2], sc1, sh1), 0.f);
                float y3 = fmaxf(fmaf(acc[mt][nt][3], sc1, sh1), 0.f);
                *reinterpret_cast<uint32_t*>(O + base0 + nl) = f16x2(y0, y1);
                *reinterpret_cast<uint32_t*>(O + base1 + nl) = f16x2(y2, y3);
            }
        }
    } else {
        float p0[16], p1[16];
        #pragma unroll
        for (int j = 0; j < 16; j++) { p0[j] = 0.f; p1[j] = 0.f; }
        #pragma unroll
        for (int mt = 0; mt < 2; mt++) {
            int co0 = co_base + mt * 16 + g, co1 = co0 + 8;
            float sc0 = gam[co0] * rsqrtf(var[co0] + 1e-5f);
            float sh0 = bet[co0] - mu[co0] * sc0;
            float sc1 = gam[co1] * rsqrtf(var[co1] + 1e-5f);
            float sh1 = bet[co1] - mu[co1] * sc1;
            float wa0 = w4[co0 * 8 + h], wb0 = w4[2048 + co0 * 8 + h];
            float wa1 = w4[co1 * 8 + h], wb1 = w4[2048 + co1 * 8 + h];
            #pragma unroll
            for (int nt = 0; nt < 8; nt++) {
                float y0 = fmaxf(fmaf(acc[mt][nt][0], sc0, sh0), 0.f);
                float y1 = fmaxf(fmaf(acc[mt][nt][1], sc0, sh0), 0.f);
                float y2 = fmaxf(fmaf(acc[mt][nt][2], sc1, sh1), 0.f);
                float y3 = fmaxf(fmaf(acc[mt][nt][3], sc1, sh1), 0.f);
                p0[nt * 2]     += y0 * wa0 + y2 * wa1;
                p0[nt * 2 + 1] += y1 * wa0 + y3 * wa1;
                p1[nt * 2]     += y0 * wb0 + y2 * wb1;
                p1[nt * 2 + 1] += y1 * wb0 + y3 * wb1;
            }
        }
        #pragma unroll
        for (int off = 4; off <= 16; off <<= 1) {
            #pragma unroll
            for (int j = 0; j < 16; j++) {
                p0[j] += __shfl_xor_sync(0xffffffffu, p0[j], off);
                p1[j] += __shfl_xor_sync(0xffffffffu, p1[j], off);
            }
        }
        if (g == 0) {
            #pragma unroll
            for (int j = 0; j < 16; j++) {
                int nl = wn * 64 + (j >> 1) * 8 + 2 * t + (j & 1);
                atomicAdd(&s_part[nl * 2],     p0[j]);
                atomicAdd(&s_part[nl * 2 + 1], p1[j]);
            }
        }
        __syncthreads();
        {
            int nl = tid >> 1, ch = tid & 1;
            atomicAdd(dout + (size_t)(b0 + nl) * 28 + w_pos * 2 + ch, s_part[tid]);
        }
    }
}

// ======================= host launch =======================
extern "C" void kernel_launch(void* const* d_in, const int* in_sizes, int n_in,
                              void* d_out, int out_size)
{
    (void)n_in;
    const float* x   = (const float*)d_in[0];
    const float* sig = (const float*)d_in[1];
    const float* w1  = (const float*)d_in[2];
    const float *w2, *w3, *w4;
    const float *g1,*b1,*m1,*v1,*g2,*b2,*m2,*v2,*g3,*b3,*m3,*v3;

    if (in_sizes[3] == 73728) {
        w2=(const float*)d_in[3];  w3=(const float*)d_in[4];  w4=(const float*)d_in[5];
        g1=(const float*)d_in[6];  b1=(const float*)d_in[7];  m1=(const float*)d_in[8];  v1=(const float*)d_in[9];
        g2=(const float*)d_in[10]; b2=(const float*)d_in[11]; m2=(const float*)d_in[12]; v2=(const float*)d_in[13];
        g3=(const float*)d_in[14]; b3=(const float*)d_in[15]; m3=(const float*)d_in[16]; v3=(const float*)d_in[17];
    } else {
        g1=(const float*)d_in[3];  b1=(const float*)d_in[4];  m1=(const float*)d_in[5];  v1=(const float*)d_in[6];
        w2=(const float*)d_in[7];
        g2=(const float*)d_in[8];  b2=(const float*)d_in[9];  m2=(const float*)d_in[10]; v2=(const float*)d_in[11];
        w3=(const float*)d_in[12];
        g3=(const float*)d_in[13]; b3=(const float*)d_in[14]; m3=(const float*)d_in[15]; v3=(const float*)d_in[16];
        w4=(const float*)d_in[17];
    }

    __half *a1, *a2, *w2h, *w3h;
    cudaGetSymbolAddress((void**)&a1, g_a1);
    cudaGetSymbolAddress((void**)&a2, g_a2);
    cudaGetSymbolAddress((void**)&w2h, g_w2);
    cudaGetSymbolAddress((void**)&w3h, g_w3);

    cudaFuncSetAttribute(conv_mma<34, 9, false, false>,
                         cudaFuncAttributeMaxDynamicSharedMemorySize, SMEM_TOT);
    cudaFuncSetAttribute(conv_mma<18, 18, true, true>,
                         cudaFuncAttributeMaxDynamicSharedMemorySize, SMEM_TOT);

    // 0) zero output accumulator (conv4 adds atomically)
    zero_out_kernel<<<(out_size + 1023) / 1024, 1024>>>((float*)d_out, out_size);
    // 1) input -> padded fp16 CHWN
    prep_input_kernel<<<896, 256>>>(x, sig);
    // 2) weights -> fp16 (w1 padded to K=32)
    cvt_w1_kernel<<<8, 256>>>(w1);
    cvt_w_kernel<<<(73728 + 255) / 256, 256>>>(w2, w2h, 73728);
    cvt_w_kernel<<<(294912 + 255) / 256, 256>>>(w3, w3h, 294912);
    // 3) conv1 via mma -> a1 (fp16 CHWN)
    conv1_mma<<<dim3(32, 112), 256>>>(g1, b1, m1, v1);
    // 4) conv2 (fp16 mma, K-chunk 64, pipelined) -> a2
    conv_mma<34, 9, false, false><<<dim3(16, 224), 256, SMEM_TOT>>>(
        a1, w2h, g2, b2, m2, v2, nullptr, a2, nullptr, 18);
    // 5) conv3 (fp16 mma, mtile paired in x for L2) + fused conv4 -> d_out
    conv_mma<18, 18, true, true><<<dim3(16, 224), 256, SMEM_TOT>>>(
        a2, w3h, g3, b3, m3, v3, w4, nullptr, (float*)d_out, 0);
}

// round 14
// speedup vs baseline: 1.1119x; 1.1119x over previous
#include <cuda_runtime.h>
#include <cuda_fp16.h>
#include <cstdint>

typedef unsigned long long ull;

#define B_N 2048

// ---------------- device scratch (zero-init at load; pad cells never written) ----
__device__ __half g_in0h[2 * 65 * 16 * 2048];                // conv1 input fp16, padded CHWN
__device__ __half g_a1[(size_t)64 * 34 * 16 * 2048];         // conv1 out (fp16)
__device__ __half g_a2[(size_t)128 * 18 * 16 * 2048];        // conv2 out (fp16)
__device__ __half g_w1p[64 * 32];                            // conv1 weights, K padded 18->32
__device__ __half g_w2[128 * 576];
__device__ __half g_w3[256 * 1152];

// ---------------- helpers ----------------
__device__ __forceinline__ uint32_t smem_u32(const void* p) {
    uint32_t a;
    asm("{ .reg .u64 t; cvta.to.shared.u64 t, %1; cvt.u32.u64 %0, t; }"
        : "=r"(a) : "l"(p));
    return a;
}
__device__ __forceinline__ uint32_t f16x2(float y0, float y1) {
    __half2 h = __floats2half2_rn(y0, y1);      // y0 -> low half
    return *reinterpret_cast<uint32_t*>(&h);
}

// ldmatrix / mma.sync (base ISA)
__device__ __forceinline__ void ldsm4(uint32_t* r, uint32_t a) {
    asm volatile("ldmatrix.sync.aligned.m8n8.x4.shared.b16 {%0,%1,%2,%3}, [%4];"
        : "=r"(r[0]), "=r"(r[1]), "=r"(r[2]), "=r"(r[3]) : "r"(a));
}
__device__ __forceinline__ void ldsm4t(uint32_t* r, uint32_t a) {
    asm volatile("ldmatrix.sync.aligned.m8n8.x4.trans.shared.b16 {%0,%1,%2,%3}, [%4];"
        : "=r"(r[0]), "=r"(r[1]), "=r"(r[2]), "=r"(r[3]) : "r"(a));
}
__device__ __forceinline__ void mma16816(float* d, const uint32_t* a, const uint32_t* b) {
    asm volatile(
        "mma.sync.aligned.m16n8k16.row.col.f32.f16.f16.f32 "
        "{%0,%1,%2,%3}, {%4,%5,%6,%7}, {%8,%9}, {%0,%1,%2,%3};"
        : "+f"(d[0]), "+f"(d[1]), "+f"(d[2]), "+f"(d[3])
        : "r"(a[0]), "r"(a[1]), "r"(a[2]), "r"(a[3]), "r"(b[0]), "r"(b[1]));
}

// cp.async
#define CP_ASYNC16(dst, src) \
    asm volatile("cp.async.cg.shared.global [%0], [%1], 16;" :: "r"(dst), "l"(src))
#define CP_COMMIT() asm volatile("cp.async.commit_group;" ::: "memory")
#define CP_WAIT0()  asm volatile("cp.async.wait_group 0;" ::: "memory")
#define CP_WAIT1()  asm volatile("cp.async.wait_group 1;" ::: "memory")

// ======================= small prep kernels =======================
__global__ void zero_out_kernel(float* p, int n) {
    int i = blockIdx.x * 1024 + threadIdx.x;
    if (i < n) p[i] = 0.f;
}

// x,sigmas [B][64][14] -> g_in0h [2][65][16][B] fp16
__global__ void prep_input_kernel(const float* __restrict__ x,
                                  const float* __restrict__ sig) {
    int fk = blockIdx.x;            // 0..895
    int f = fk / 14, k = fk % 14;
    int t = threadIdx.x;
    for (int it = 0; it < 8; it++) {
        int b = it * 256 + t;
        float xv = x[(size_t)b * 896 + fk];
        float sv = sig[(size_t)b * 896 + fk] * 10.0f;
        g_in0h[((size_t)(0 * 65 + f + 1) * 16 + k + 1) * B_N + b] = __float2half_rn(xv);
        g_in0h[((size_t)(1 * 65 + f + 1) * 16 + k + 1) * B_N + b] = __float2half_rn(sv);
    }
}

// fp32 weights -> fp16 (single limb)
__global__ void cvt_w_kernel(const float* __restrict__ w, __half* __restrict__ o, int n) {
    int i = blockIdx.x * 256 + threadIdx.x;
    if (i >= n) return;
    o[i] = __float2half_rn(w[i]);
}

// conv1 weights [64][2][3][3] -> [64co][32k] fp16, zeros for k>=18
__global__ void cvt_w1_kernel(const float* __restrict__ w1) {
    int i = blockIdx.x * 256 + threadIdx.x;
    if (i >= 2048) return;
    int co = i >> 5, k = i & 31;
    g_w1p[i] = (k < 18) ? __float2half_rn(w1[co * 18 + k]) : __half(0.f);
}

// ======================= conv1 via mma, pipelined over h =====================
// Grid (4 h-groups, 112 n-tiles).  Each CTA: A staged once, loops 8 h values
// with double-buffered cp.async B staging (rows 0..17 real, 18..31 zero-filled
// once).  256 threads, 8 warps as 2m x 4n (warp = 32co x 64n).
// smem: A [64][40h] pitch 80B @0 (5120B); B bufs [32][264h] pitch 528B
//       @5120 and @22016 (16896B each).  Total 38912B static.
__global__ void __launch_bounds__(256, 2)
conv1_mma(const float* __restrict__ g1, const float* __restrict__ b1,
          const float* __restrict__ m1, const float* __restrict__ v1)
{
    __shared__ __align__(16) char smem[38912];
    const uint32_t smb = smem_u32(smem);
    const int OFF_B0 = 5120, BSZ = 16896;

    const int tid  = threadIdx.x;
    const int lane = tid & 31, wid = tid >> 5;
    const int wm = wid & 1, wn = wid >> 1;          // 2m x 4n warps
    const int g = lane >> 2, t = lane & 3;
    const int h0 = blockIdx.x * 8;                  // h group
    const int n0 = blockIdx.y * 256;
    const int w_pos = n0 >> 11;
    const int b0    = n0 & 2047;

    // zero-fill pad k-rows 18..31 of BOTH B buffers (done once)
    {
        uint4 z = make_uint4(0u, 0u, 0u, 0u);
        for (int e = tid; e < 14 * 32 * 2; e += 256) {
            int buf = e >= 448;
            int ee  = buf ? e - 448 : e;
            int row = 18 + (ee >> 5), q = ee & 31;
            *reinterpret_cast<uint4*>(smem + OFF_B0 + buf * BSZ + row * 528 + q * 16) = z;
        }
    }
    // stage A (64 rows x 64B) + B for h0 (rows 0..17)
    {
        int row = tid >> 2, q = tid & 3;
        CP_ASYNC16(smb + (uint32_t)(row * 80 + q * 16), g_w1p + row * 32 + q * 8);
    }
    auto stageB = [&](int h, uint32_t bufOff) {
        #pragma unroll
        for (int it = 0; it < 3; it++) {
            int e = it * 256 + tid;                 // 0..767, use 0..575
            if (e < 576) {
                int row = e >> 5, n16 = e & 31;     // row 0..17
                int ci = row / 9;
                int r9 = row - ci * 9;
                int kh = r9 / 3;
                int kw = r9 - kh * 3;
                const __half* src =
                    g_in0h + ((size_t)(ci * 65 + 2 * h + kh) * 16 + w_pos + kw) * B_N
                           + b0 + n16 * 8;
                CP_ASYNC16(smb + bufOff + (uint32_t)(row * 528 + n16 * 16), src);
            }
        }
        CP_COMMIT();
    };
    stageB(h0, OFF_B0);

    const int rA = lane & 15;
    const int kA = (lane >> 4) << 3;
    const uint32_t aA0 = smb + (uint32_t)((wm * 32 +  0 + rA) * 80 + kA * 2);
    const uint32_t aA1 = smb + (uint32_t)((wm * 32 + 16 + rA) * 80 + kA * 2);
    const uint32_t bLane = (uint32_t)((lane & 15) * 528 + (lane >> 4) * 16 + wn * 128);

    #pragma unroll 1
    for (int i = 0; i < 8; i++) {
        const int h = h0 + i;
        const uint32_t cur = OFF_B0 + (i & 1) * BSZ;
        if (i + 1 < 8) {
            stageB(h + 1, OFF_B0 + ((i + 1) & 1) * BSZ);
            CP_WAIT1();
        } else {
            CP_WAIT0();
        }
        __syncthreads();

        float acc[2][8][4];
        #pragma unroll
        for (int mt = 0; mt < 2; mt++)
            #pragma unroll
            for (int nt = 0; nt < 8; nt++)
                #pragma unroll
                for (int j = 0; j < 4; j++) acc[mt][nt][j] = 0.f;

        const uint32_t bA = smb + cur + bLane;
        #pragma unroll
        for (int ks = 0; ks < 2; ks++) {
            uint32_t Ah0[4], Ah1[4];
            ldsm4(Ah0, aA0 + ks * 32);
            ldsm4(Ah1, aA1 + ks * 32);
            #pragma unroll
            for (int ntp = 0; ntp < 4; ntp++) {
                uint32_t bf[4];
                ldsm4t(bf, bA + ks * (16 * 528) + ntp * 32);
                mma16816(acc[0][2 * ntp],     Ah0, bf);
                mma16816(acc[1][2 * ntp],     Ah1, bf);
                mma16816(acc[0][2 * ntp + 1], Ah0, bf + 2);
                mma16816(acc[1][2 * ntp + 1], Ah1, bf + 2);
            }
        }

        // epilogue: BN + ReLU -> g_a1 [64][34][16][B]
        #pragma unroll
        for (int mt = 0; mt < 2; mt++) {
            int co0 = wm * 32 + mt * 16 + g, co1 = co0 + 8;
            float sc0 = g1[co0] * rsqrtf(v1[co0] + 1e-5f);
            float sh0 = b1[co0] - m1[co0] * sc0;
            float sc1 = g1[co1] * rsqrtf(v1[co1] + 1e-5f);
            float sh1 = b1[co1] - m1[co1] * sc1;
            size_t base0 = ((size_t)(co0 * 34 + h + 1) * 16 + w_pos + 1) * B_N + b0;
            size_t base1 = ((size_t)(co1 * 34 + h + 1) * 16 + w_pos + 1) * B_N + b0;
            #pragma unroll
            for (int nt = 0; nt < 8; nt++) {
                int nl = wn * 64 + nt * 8 + 2 * t;
                float y0 = fmaxf(fmaf(acc[mt][nt][0], sc0, sh0), 0.f);
                float y1 = fmaxf(fmaf(acc[mt][nt][1], sc0, sh0), 0.f);
                float y2 = fmaxf(fmaf(acc[mt][nt][2], sc1, sh1), 0.f);
                float y3 = fmaxf(fmaf(acc[mt][nt][3], sc1, sh1), 0.f);
                *reinterpret_cast<uint32_t*>(g_a1 + base0 + nl) = f16x2(y0, y1);
                *reinterpret_cast<uint32_t*>(g_a1 + base1 + nl) = f16x2(y2, y3);
            }
        }
        __syncthreads();    // protect cur buffer before it is re-staged
    }
}

// ======================= mma.sync conv GEMM v8 (fp16, K-chunk 64) ==========
// CTA: D[128 co][128 n], K-chunk 64, 256 threads (8 warps, 4m x 2n).
// cp.async double-buffered.  MSPLIT: blockIdx.x = h*2 + mtile (L2 pairing).
// Per-buffer: A [128][72h] @0 (pitch 144B), B [64][136h] @18432 (pitch 272B).
static constexpr int OFF_B_L   = 18432;
static constexpr int BUF_SZ    = 35840;
static constexpr int OFF_PART  = 2 * BUF_SZ;        // 256 floats (FUSE4)
static constexpr int SMEM_TOT  = OFF_PART + 1024;   // 72704

template<int HPIN, int CHUNKS, bool FUSE4, bool MSPLIT>
__global__ void __launch_bounds__(256, 2)
conv_mma(const __half* __restrict__ X,
         const __half* __restrict__ W,
         const float* __restrict__ gam, const float* __restrict__ bet,
         const float* __restrict__ mu,  const float* __restrict__ var,
         const float* __restrict__ w4,
         __half* __restrict__ O,
         float* __restrict__ dout, int HP_OUT)
{
    constexpr int KTOT = CHUNKS * 64;
    extern __shared__ __align__(16) char smem[];
    const uint32_t smb = smem_u32(smem);
    float* s_part = reinterpret_cast<float*>(smem + OFF_PART);

    const int tid  = threadIdx.x;
    const int lane = tid & 31, wid = tid >> 5;
    const int wm = wid & 3, wn = wid >> 2;          // 4m x 2n warps
    const int g = lane >> 2, t = lane & 3;
    const int h     = MSPLIT ? (blockIdx.x >> 1) : blockIdx.x;
    const int mtile = MSPLIT ? (blockIdx.x & 1) : 0;
    const int n0 = blockIdx.y * 128;
    const int w_pos = n0 >> 11;
    const int b0    = n0 & 2047;

    if (FUSE4) s_part[tid] = 0.f;

    const int rA = lane & 15;
    const int kA = (lane >> 4) << 3;
    const uint32_t aOff0 = (uint32_t)((wm * 32 +  0 + rA) * 144 + kA * 2);
    const uint32_t aOff1 = (uint32_t)((wm * 32 + 16 + rA) * 144 + kA * 2);
    const uint32_t bOff  = (uint32_t)(OFF_B_L + (lane & 15) * 272
                                      + (lane >> 4) * 16 + wn * 128);

    float acc[2][8][4];
    #pragma unroll
    for (int mt = 0; mt < 2; mt++)
        #pragma unroll
        for (int nt = 0; nt < 8; nt++)
            #pragma unroll
            for (int i = 0; i < 4; i++) acc[mt][nt][i] = 0.f;

    auto stage = [&](int cc, uint32_t bufOff) {
        #pragma unroll
        for (int it = 0; it < 4; it++) {
            int e = it * 256 + tid;                 // 0..1023
            int row = e >> 3, q = e & 7;
            size_t go = (size_t)(mtile * 128 + row) * KTOT + cc * 64 + q * 8;
            uint32_t so = smb + bufOff + (uint32_t)(row * 144 + q * 16);
            CP_ASYNC16(so, W + go);
        }
        #pragma unroll
        for (int it = 0; it < 4; it++) {
            int e = it * 256 + tid;                 // 0..1023
            int row = e >> 4, n16 = e & 15;
            int k = cc * 64 + row;
            int ci = k / 9;
            int r9 = k - ci * 9;
            int kh = r9 / 3;
            int kw = r9 - kh * 3;
            size_t go = ((size_t)(ci * HPIN + 2 * h + kh) * 16 + w_pos + kw) * B_N
                        + b0 + n16 * 8;
            uint32_t so = smb + bufOff + (uint32_t)(OFF_B_L + row * 272 + n16 * 16);
            CP_ASYNC16(so, X + go);
        }
        CP_COMMIT();
    };

    stage(0, 0);

    #pragma unroll 1
    for (int c = 0; c < CHUNKS; c++) {
        const uint32_t cur = (c & 1) ? BUF_SZ : 0;
        if (c + 1 < CHUNKS) {
            stage(c + 1, cur ^ BUF_SZ);
            CP_WAIT1();
        } else {
            CP_WAIT0();
        }
        __syncthreads();

        const uint32_t aHi0 = smb + cur + aOff0;
        const uint32_t aHi1 = smb + cur + aOff1;
        const uint32_t bA   = smb + cur + bOff;
        #pragma unroll
        for (int ks = 0; ks < 4; ks++) {
            uint32_t Ah0[4], Ah1[4];
            ldsm4(Ah0, aHi0 + ks * 32);
            ldsm4(Ah1, aHi1 + ks * 32);
            #pragma unroll
            for (int ntp = 0; ntp < 4; ntp++) {
                uint32_t bf[4];
                ldsm4t(bf, bA + ks * (16 * 272) + ntp * 32);
                mma16816(acc[0][2 * ntp],     Ah0, bf);
                mma16816(acc[1][2 * ntp],     Ah1, bf);
                mma16816(acc[0][2 * ntp + 1], Ah0, bf + 2);
                mma16816(acc[1][2 * ntp + 1], Ah1, bf + 2);
            }
        }
        __syncthreads();
    }

    // ======================= epilogue =======================
    const int co_base = mtile * 128 + wm * 32;
    if (!FUSE4) {
        #pragma unroll
        for (int mt = 0; mt < 2; mt++) {
            int co0 = co_base + mt * 16 + g, co1 = co0 + 8;
            float sc0 = gam[co0] * rsqrtf(var[co0] + 1e-5f);
            float sh0 = bet[co0] - mu[co0] * sc0;
            float sc1 = gam[co1] * rsqrtf(var[co1] + 1e-5f);
            float sh1 = bet[co1] - mu[co1] * sc1;
            size_t base0 = ((size_t)(co0 * HP_OUT + h + 1) * 16 + w_pos + 1) * B_N + b0;
            size_t base1 = ((size_t)(co1 * HP_OUT + h + 1) * 16 + w_pos + 1) * B_N + b0;
            #pragma unroll
            for (int nt = 0; nt < 8; nt++) {
                int nl = wn * 64 + nt * 8 + 2 * t;
                float y0 = fmaxf(fmaf(acc[mt][nt][0], sc0, sh0), 0.f);
                float y1 = fmaxf(fmaf(acc[mt][nt][1], sc0, sh0), 0.f);
                float y2 = fmaxf(fmaf(acc[mt][nt][2], sc1, sh1), 0.f);
                float y3 = fmaxf(fmaf(acc[mt][nt][3], sc1, sh1), 0.f);
                *reinterpret_cast<uint32_t*>(O + base0 + nl) = f16x2(y0, y1);
                *reinterpret_cast<uint32_t*>(O + base1 + nl) = f16x2(y2, y3);
            }
        }
    } else {
        float p0[16], p1[16];
        #pragma unroll
        for (int j = 0; j < 16; j++) { p0[j] = 0.f; p1[j] = 0.f; }
        #pragma unroll
        for (int mt = 0; mt < 2; mt++) {
            int co0 = co_base + mt * 16 + g, co1 = co0 + 8;
            float sc0 = gam[co0] * rsqrtf(var[co0] + 1e-5f);
            float sh0 = bet[co0] - mu[co0] * sc0;
            float sc1 = gam[co1] * rsqrtf(var[co1] + 1e-5f);
            float sh1 = bet[co1] - mu[co1] * sc1;
            float wa0 = w4[co0 * 8 + h], wb0 = w4[2048 + co0 * 8 + h];
            float wa1 = w4[co1 * 8 + h], wb1 = w4[2048 + co1 * 8 + h];
            #pragma unroll
            for (int nt = 0; nt < 8; nt++) {
                float y0 = fmaxf(fmaf(acc[mt][nt][0], sc0, sh0), 0.f);
                float y1 = fmaxf(fmaf(acc[mt][nt][1], sc0, sh0), 0.f);
                float y2 = fmaxf(fmaf(acc[mt][nt][2], sc1, sh1), 0.f);
                float y3 = fmaxf(fmaf(acc[mt][nt][3], sc1, sh1), 0.f);
                p0[nt * 2]     += y0 * wa0 + y2 * wa1;
                p0[nt * 2 + 1] += y1 * wa0 + y3 * wa1;
                p1[nt * 2]     += y0 * wb0 + y2 * wb1;
                p1[nt * 2 + 1] += y1 * wb0 + y3 * wb1;
            }
        }
        #pragma unroll
        for (int off = 4; off <= 16; off <<= 1) {
            #pragma unroll
            for (int j = 0; j < 16; j++) {
                p0[j] += __shfl_xor_sync(0xffffffffu, p0[j], off);
                p1[j] += __shfl_xor_sync(0xffffffffu, p1[j], off);
            }
        }
        if (g == 0) {
            #pragma unroll
            for (int j = 0; j < 16; j++) {
                int nl = wn * 64 + (j >> 1) * 8 + 2 * t + (j & 1);
                atomicAdd(&s_part[nl * 2],     p0[j]);
                atomicAdd(&s_part[nl * 2 + 1], p1[j]);
            }
        }
        __syncthreads();
        {
            int nl = tid >> 1, ch = tid & 1;
            atomicAdd(dout + (size_t)(b0 + nl) * 28 + w_pos * 2 + ch, s_part[tid]);
        }
    }
}

// ======================= host launch =======================
extern "C" void kernel_launch(void* const* d_in, const int* in_sizes, int n_in,
                              void* d_out, int out_size)
{
    (void)n_in;
    const float* x   = (const float*)d_in[0];
    const float* sig = (const float*)d_in[1];
    const float* w1  = (const float*)d_in[2];
    const float *w2, *w3, *w4;
    const float *g1,*b1,*m1,*v1,*g2,*b2,*m2,*v2,*g3,*b3,*m3,*v3;

    if (in_sizes[3] == 73728) {
        w2=(const float*)d_in[3];  w3=(const float*)d_in[4];  w4=(const float*)d_in[5];
        g1=(const float*)d_in[6];  b1=(const float*)d_in[7];  m1=(const float*)d_in[8];  v1=(const float*)d_in[9];
        g2=(const float*)d_in[10]; b2=(const float*)d_in[11]; m2=(const float*)d_in[12]; v2=(const float*)d_in[13];
        g3=(const float*)d_in[14]; b3=(const float*)d_in[15]; m3=(const float*)d_in[16]; v3=(const float*)d_in[17];
    } else {
        g1=(const float*)d_in[3];  b1=(const float*)d_in[4];  m1=(const float*)d_in[5];  v1=(const float*)d_in[6];
        w2=(const float*)d_in[7];
        g2=(const float*)d_in[8];  b2=(const float*)d_in[9];  m2=(const float*)d_in[10]; v2=(const float*)d_in[11];
        w3=(const float*)d_in[12];
        g3=(const float*)d_in[13]; b3=(const float*)d_in[14]; m3=(const float*)d_in[15]; v3=(const float*)d_in[16];
        w4=(const float*)d_in[17];
    }

    __half *a1, *a2, *w2h, *w3h;
    cudaGetSymbolAddress((void**)&a1, g_a1);
    cudaGetSymbolAddress((void**)&a2, g_a2);
    cudaGetSymbolAddress((void**)&w2h, g_w2);
    cudaGetSymbolAddress((void**)&w3h, g_w3);

    cudaFuncSetAttribute(conv_mma<34, 9, false, false>,
                         cudaFuncAttributeMaxDynamicSharedMemorySize, SMEM_TOT);
    cudaFuncSetAttribute(conv_mma<18, 18, true, true>,
                         cudaFuncAttributeMaxDynamicSharedMemorySize, SMEM_TOT);

    // 0) zero output accumulator (conv4 adds atomically)
    zero_out_kernel<<<(out_size + 1023) / 1024, 1024>>>((float*)d_out, out_size);
    // 1) input -> padded fp16 CHWN
    prep_input_kernel<<<896, 256>>>(x, sig);
    // 2) weights -> fp16 (w1 padded to K=32)
    cvt_w1_kernel<<<8, 256>>>(w1);
    cvt_w_kernel<<<(73728 + 255) / 256, 256>>>(w2, w2h, 73728);
    cvt_w_kernel<<<(294912 + 255) / 256, 256>>>(w3, w3h, 294912);
    // 3) conv1 via mma, pipelined over h -> a1 (fp16 CHWN)
    conv1_mma<<<dim3(4, 112), 256>>>(g1, b1, m1, v1);
    // 4) conv2 (fp16 mma, K-chunk 64, pipelined) -> a2
    conv_mma<34, 9, false, false><<<dim3(16, 224), 256, SMEM_TOT>>>(
        a1, w2h, g2, b2, m2, v2, nullptr, a2, nullptr, 18);
    // 5) conv3 (fp16 mma, mtile paired in x for L2) + fused conv4 -> d_out
    conv_mma<18, 18, true, true><<<dim3(16, 224), 256, SMEM_TOT>>>(
        a2, w3h, g3, b3, m3, v3, w4, nullptr, (float*)d_out, 0);
}

// round 15
// speedup vs baseline: 1.1245x; 1.0114x over previous
#include <cuda_runtime.h>
#include <cuda_fp16.h>
#include <cstdint>

typedef unsigned long long ull;

#define B_N 2048

// ---------------- device scratch (zero-init at load; pad cells never written) ----
__device__ __half g_in0h[2 * 65 * 16 * 2048];                // conv1 input fp16, padded CHWN
__device__ __half g_a1[(size_t)64 * 34 * 16 * 2048];         // conv1 out (fp16)
__device__ __half g_a2[(size_t)128 * 18 * 16 * 2048];        // conv2 out (fp16)
__device__ __half g_w1p[64 * 32];                            // conv1 weights, K padded 18->32
__device__ __half g_w2[128 * 576];
__device__ __half g_w3[256 * 1152];

// ---------------- helpers ----------------
__device__ __forceinline__ uint32_t smem_u32(const void* p) {
    uint32_t a;
    asm("{ .reg .u64 t; cvta.to.shared.u64 t, %1; cvt.u32.u64 %0, t; }"
        : "=r"(a) : "l"(p));
    return a;
}
__device__ __forceinline__ uint32_t f16x2(float y0, float y1) {
    __half2 h = __floats2half2_rn(y0, y1);      // y0 -> low half
    return *reinterpret_cast<uint32_t*>(&h);
}

// ldmatrix / mma.sync (base ISA)
__device__ __forceinline__ void ldsm4(uint32_t* r, uint32_t a) {
    asm volatile("ldmatrix.sync.aligned.m8n8.x4.shared.b16 {%0,%1,%2,%3}, [%4];"
        : "=r"(r[0]), "=r"(r[1]), "=r"(r[2]), "=r"(r[3]) : "r"(a));
}
__device__ __forceinline__ void ldsm4t(uint32_t* r, uint32_t a) {
    asm volatile("ldmatrix.sync.aligned.m8n8.x4.trans.shared.b16 {%0,%1,%2,%3}, [%4];"
        : "=r"(r[0]), "=r"(r[1]), "=r"(r[2]), "=r"(r[3]) : "r"(a));
}
__device__ __forceinline__ void mma16816(float* d, const uint32_t* a, const uint32_t* b) {
    asm volatile(
        "mma.sync.aligned.m16n8k16.row.col.f32.f16.f16.f32 "
        "{%0,%1,%2,%3}, {%4,%5,%6,%7}, {%8,%9}, {%0,%1,%2,%3};"
        : "+f"(d[0]), "+f"(d[1]), "+f"(d[2]), "+f"(d[3])
        : "r"(a[0]), "r"(a[1]), "r"(a[2]), "r"(a[3]), "r"(b[0]), "r"(b[1]));
}

// cp.async
#define CP_ASYNC16(dst, src) \
    asm volatile("cp.async.cg.shared.global [%0], [%1], 16;" :: "r"(dst), "l"(src))
#define CP_COMMIT() asm volatile("cp.async.commit_group;" ::: "memory")
#define CP_WAIT0()  asm volatile("cp.async.wait_group 0;" ::: "memory")
#define CP_WAIT1()  asm volatile("cp.async.wait_group 1;" ::: "memory")

// ======================= merged prep kernel =======================
// One launch: zero d_out, cvt w1 (pad K to 32), cvt w2, cvt w3.
__global__ void prep_all_kernel(float* dout, int nz,
                                const float* __restrict__ w1,
                                const float* __restrict__ w2,
                                const float* __restrict__ w3)
{
    int i = blockIdx.x * 256 + threadIdx.x;         // 0 .. 294912
    if (i < 294912) g_w3[i] = __float2half_rn(w3[i]);
    if (i < 73728)  g_w2[i] = __float2half_rn(w2[i]);
    if (i < 2048) {
        int co = i >> 5, k = i & 31;
        g_w1p[i] = (k < 18) ? __float2half_rn(w1[co * 18 + k]) : __half(0.f);
    }
    if (i < nz) dout[i] = 0.f;
}

// x,sigmas [B][64][14] -> g_in0h [2][65][16][B] fp16
__global__ void prep_input_kernel(const float* __restrict__ x,
                                  const float* __restrict__ sig) {
    int fk = blockIdx.x;            // 0..895
    int f = fk / 14, k = fk % 14;
    int t = threadIdx.x;
    for (int it = 0; it < 8; it++) {
        int b = it * 256 + t;
        float xv = x[(size_t)b * 896 + fk];
        float sv = sig[(size_t)b * 896 + fk] * 10.0f;
        g_in0h[((size_t)(0 * 65 + f + 1) * 16 + k + 1) * B_N + b] = __float2half_rn(xv);
        g_in0h[((size_t)(1 * 65 + f + 1) * 16 + k + 1) * B_N + b] = __float2half_rn(sv);
    }
}

// ======================= conv1 via mma, pipelined over h =====================
// Grid (4 h-groups, 112 n-tiles).  A staged once; loops 8 h values with
// double-buffered cp.async B staging.  8 warps as 2m x 4n (warp 32co x 64n).
__global__ void __launch_bounds__(256, 2)
conv1_mma(const float* __restrict__ g1, const float* __restrict__ b1,
          const float* __restrict__ m1, const float* __restrict__ v1)
{
    __shared__ __align__(16) char smem[38912];
    const uint32_t smb = smem_u32(smem);
    const int OFF_B0 = 5120, BSZ = 16896;

    const int tid  = threadIdx.x;
    const int lane = tid & 31, wid = tid >> 5;
    const int wm = wid & 1, wn = wid >> 1;          // 2m x 4n warps
    const int g = lane >> 2, t = lane & 3;
    const int h0 = blockIdx.x * 8;
    const int n0 = blockIdx.y * 256;
    const int w_pos = n0 >> 11;
    const int b0    = n0 & 2047;

    // zero-fill pad k-rows 18..31 of BOTH B buffers (once)
    {
        uint4 z = make_uint4(0u, 0u, 0u, 0u);
        for (int e = tid; e < 14 * 32 * 2; e += 256) {
            int buf = e >= 448;
            int ee  = buf ? e - 448 : e;
            int row = 18 + (ee >> 5), q = ee & 31;
            *reinterpret_cast<uint4*>(smem + OFF_B0 + buf * BSZ + row * 528 + q * 16) = z;
        }
    }
    // stage A (64 rows x 64B)
    {
        int row = tid >> 2, q = tid & 3;
        CP_ASYNC16(smb + (uint32_t)(row * 80 + q * 16), g_w1p + row * 32 + q * 8);
    }
    auto stageB = [&](int h, uint32_t bufOff) {
        #pragma unroll
        for (int it = 0; it < 3; it++) {
            int e = it * 256 + tid;
            if (e < 576) {
                int row = e >> 5, n16 = e & 31;     // row 0..17
                int ci = row / 9;
                int r9 = row - ci * 9;
                int kh = r9 / 3;
                int kw = r9 - kh * 3;
                const __half* src =
                    g_in0h + ((size_t)(ci * 65 + 2 * h + kh) * 16 + w_pos + kw) * B_N
                           + b0 + n16 * 8;
                CP_ASYNC16(smb + bufOff + (uint32_t)(row * 528 + n16 * 16), src);
            }
        }
        CP_COMMIT();
    };
    stageB(h0, OFF_B0);

    const int rA = lane & 15;
    const int kA = (lane >> 4) << 3;
    const uint32_t aA0 = smb + (uint32_t)((wm * 32 +  0 + rA) * 80 + kA * 2);
    const uint32_t aA1 = smb + (uint32_t)((wm * 32 + 16 + rA) * 80 + kA * 2);
    const uint32_t bLane = (uint32_t)((lane & 15) * 528 + (lane >> 4) * 16 + wn * 128);

    #pragma unroll 1
    for (int i = 0; i < 8; i++) {
        const int h = h0 + i;
        const uint32_t cur = OFF_B0 + (i & 1) * BSZ;
        if (i + 1 < 8) {
            stageB(h + 1, OFF_B0 + ((i + 1) & 1) * BSZ);
            CP_WAIT1();
        } else {
            CP_WAIT0();
        }
        __syncthreads();

        float acc[2][8][4];
        #pragma unroll
        for (int mt = 0; mt < 2; mt++)
            #pragma unroll
            for (int nt = 0; nt < 8; nt++)
                #pragma unroll
                for (int j = 0; j < 4; j++) acc[mt][nt][j] = 0.f;

        const uint32_t bA = smb + cur + bLane;
        #pragma unroll
        for (int ks = 0; ks < 2; ks++) {
            uint32_t Ah0[4], Ah1[4];
            ldsm4(Ah0, aA0 + ks * 32);
            ldsm4(Ah1, aA1 + ks * 32);
            #pragma unroll
            for (int ntp = 0; ntp < 4; ntp++) {
                uint32_t bf[4];
                ldsm4t(bf, bA + ks * (16 * 528) + ntp * 32);
                mma16816(acc[0][2 * ntp],     Ah0, bf);
                mma16816(acc[1][2 * ntp],     Ah1, bf);
                mma16816(acc[0][2 * ntp + 1], Ah0, bf + 2);
                mma16816(acc[1][2 * ntp + 1], Ah1, bf + 2);
            }
        }

        // epilogue: BN + ReLU -> g_a1 [64][34][16][B]
        #pragma unroll
        for (int mt = 0; mt < 2; mt++) {
            int co0 = wm * 32 + mt * 16 + g, co1 = co0 + 8;
            float sc0 = g1[co0] * rsqrtf(v1[co0] + 1e-5f);
            float sh0 = b1[co0] - m1[co0] * sc0;
            float sc1 = g1[co1] * rsqrtf(v1[co1] + 1e-5f);
            float sh1 = b1[co1] - m1[co1] * sc1;
            size_t base0 = ((size_t)(co0 * 34 + h + 1) * 16 + w_pos + 1) * B_N + b0;
            size_t base1 = ((size_t)(co1 * 34 + h + 1) * 16 + w_pos + 1) * B_N + b0;
            #pragma unroll
            for (int nt = 0; nt < 8; nt++) {
                int nl = wn * 64 + nt * 8 + 2 * t;
                float y0 = fmaxf(fmaf(acc[mt][nt][0], sc0, sh0), 0.f);
                float y1 = fmaxf(fmaf(acc[mt][nt][1], sc0, sh0), 0.f);
                float y2 = fmaxf(fmaf(acc[mt][nt][2], sc1, sh1), 0.f);
                float y3 = fmaxf(fmaf(acc[mt][nt][3], sc1, sh1), 0.f);
                *reinterpret_cast<uint32_t*>(g_a1 + base0 + nl) = f16x2(y0, y1);
                *reinterpret_cast<uint32_t*>(g_a1 + base1 + nl) = f16x2(y2, y3);
            }
        }
        __syncthreads();
    }
}

// ======================= mma.sync conv GEMM (fp16, K-chunk 64) ==========
// CTA: D[128 co][128 n], 256 threads (8 warps, 4m x 2n).  cp.async 2-buf.
// mtile = blockIdx.z (R12 layout).  Grid x = h (L2 reuse of X across h).
static constexpr int OFF_B_L   = 18432;
static constexpr int BUF_SZ    = 35840;
static constexpr int OFF_PART  = 2 * BUF_SZ;
static constexpr int SMEM_TOT  = OFF_PART + 1024;   // 72704

template<int HPIN, int CHUNKS, bool FUSE4>
__global__ void __launch_bounds__(256, 2)
conv_mma(const __half* __restrict__ X,
         const __half* __restrict__ W,
         const float* __restrict__ gam, const float* __restrict__ bet,
         const float* __restrict__ mu,  const float* __restrict__ var,
         const float* __restrict__ w4,
         __half* __restrict__ O,
         float* __restrict__ dout, int HP_OUT)
{
    constexpr int KTOT = CHUNKS * 64;
    extern __shared__ __align__(16) char smem[];
    const uint32_t smb = smem_u32(smem);
    float* s_part = reinterpret_cast<float*>(smem + OFF_PART);

    const int tid  = threadIdx.x;
    const int lane = tid & 31, wid = tid >> 5;
    const int wm = wid & 3, wn = wid >> 2;          // 4m x 2n warps
    const int g = lane >> 2, t = lane & 3;
    const int h     = blockIdx.x;
    const int mtile = blockIdx.z;
    const int n0 = blockIdx.y * 128;
    const int w_pos = n0 >> 11;
    const int b0    = n0 & 2047;

    if (FUSE4) s_part[tid] = 0.f;

    const int rA = lane & 15;
    const int kA = (lane >> 4) << 3;
    const uint32_t aOff0 = (uint32_t)((wm * 32 +  0 + rA) * 144 + kA * 2);
    const uint32_t aOff1 = (uint32_t)((wm * 32 + 16 + rA) * 144 + kA * 2);
    const uint32_t bOff  = (uint32_t)(OFF_B_L + (lane & 15) * 272
                                      + (lane >> 4) * 16 + wn * 128);

    float acc[2][8][4];
    #pragma unroll
    for (int mt = 0; mt < 2; mt++)
        #pragma unroll
        for (int nt = 0; nt < 8; nt++)
            #pragma unroll
            for (int i = 0; i < 4; i++) acc[mt][nt][i] = 0.f;

    auto stage = [&](int cc, uint32_t bufOff) {
        #pragma unroll
        for (int it = 0; it < 4; it++) {
            int e = it * 256 + tid;
            int row = e >> 3, q = e & 7;
            size_t go = (size_t)(mtile * 128 + row) * KTOT + cc * 64 + q * 8;
            uint32_t so = smb + bufOff + (uint32_t)(row * 144 + q * 16);
            CP_ASYNC16(so, W + go);
        }
        #pragma unroll
        for (int it = 0; it < 4; it++) {
            int e = it * 256 + tid;
            int row = e >> 4, n16 = e & 15;
            int k = cc * 64 + row;
            int ci = k / 9;
            int r9 = k - ci * 9;
            int kh = r9 / 3;
            int kw = r9 - kh * 3;
            size_t go = ((size_t)(ci * HPIN + 2 * h + kh) * 16 + w_pos + kw) * B_N
                        + b0 + n16 * 8;
            uint32_t so = smb + bufOff + (uint32_t)(OFF_B_L + row * 272 + n16 * 16);
            CP_ASYNC16(so, X + go);
        }
        CP_COMMIT();
    };

    stage(0, 0);

    #pragma unroll 1
    for (int c = 0; c < CHUNKS; c++) {
        const uint32_t cur = (c & 1) ? BUF_SZ : 0;
        if (c + 1 < CHUNKS) {
            stage(c + 1, cur ^ BUF_SZ);
            CP_WAIT1();
        } else {
            CP_WAIT0();
        }
        __syncthreads();

        const uint32_t aHi0 = smb + cur + aOff0;
        const uint32_t aHi1 = smb + cur + aOff1;
        const uint32_t bA   = smb + cur + bOff;
        #pragma unroll
        for (int ks = 0; ks < 4; ks++) {
            uint32_t Ah0[4], Ah1[4];
            ldsm4(Ah0, aHi0 + ks * 32);
            ldsm4(Ah1, aHi1 + ks * 32);
            #pragma unroll
            for (int ntp = 0; ntp < 4; ntp++) {
                uint32_t bf[4];
                ldsm4t(bf, bA + ks * (16 * 272) + ntp * 32);
                mma16816(acc[0][2 * ntp],     Ah0, bf);
                mma16816(acc[1][2 * ntp],     Ah1, bf);
                mma16816(acc[0][2 * ntp + 1], Ah0, bf + 2);
                mma16816(acc[1][2 * ntp + 1], Ah1, bf + 2);
            }
        }
        __syncthreads();
    }

    // ======================= epilogue =======================
    const int co_base = mtile * 128 + wm * 32;
    if (!FUSE4) {
        #pragma unroll
        for (int mt = 0; mt < 2; mt++) {
            int co0 = co_base + mt * 16 + g, co1 = co0 + 8;
            float sc0 = gam[co0] * rsqrtf(var[co0] + 1e-5f);
            float sh0 = bet[co0] - mu[co0] * sc0;
            float sc1 = gam[co1] * rsqrtf(var[co1] + 1e-5f);
            float sh1 = bet[co1] - mu[co1] * sc1;
            size_t base0 = ((size_t)(co0 * HP_OUT + h + 1) * 16 + w_pos + 1) * B_N + b0;
            size_t base1 = ((size_t)(co1 * HP_OUT + h + 1) * 16 + w_pos + 1) * B_N + b0;
            #pragma unroll
            for (int nt = 0; nt < 8; nt++) {
                int nl = wn * 64 + nt * 8 + 2 * t;
                float y0 = fmaxf(fmaf(acc[mt][nt][0], sc0, sh0), 0.f);
                float y1 = fmaxf(fmaf(acc[mt][nt][1], sc0, sh0), 0.f);
                float y2 = fmaxf(fmaf(acc[mt][nt][2], sc1, sh1), 0.f);
                float y3 = fmaxf(fmaf(acc[mt][nt][3], sc1, sh1), 0.f);
                *reinterpret_cast<uint32_t*>(O + base0 + nl) = f16x2(y0, y1);
                *reinterpret_cast<uint32_t*>(O + base1 + nl) = f16x2(y2, y3);
            }
        }
    } else {
        float p0[16], p1[16];
        #pragma unroll
        for (int j = 0; j < 16; j++) { p0[j] = 0.f; p1[j] = 0.f; }
        #pragma unroll
        for (int mt = 0; mt < 2; mt++) {
            int co0 = co_base + mt * 16 + g, co1 = co0 + 8;
            float sc0 = gam[co0] * rsqrtf(var[co0] + 1e-5f);
            float sh0 = bet[co0] - mu[co0] * sc0;
            float sc1 = gam[co1] * rsqrtf(var[co1] + 1e-5f);
            float sh1 = bet[co1] - mu[co1] * sc1;
            float wa0 = w4[co0 * 8 + h], wb0 = w4[2048 + co0 * 8 + h];
            float wa1 = w4[co1 * 8 + h], wb1 = w4[2048 + co1 * 8 + h];
            #pragma unroll
            for (int nt = 0; nt < 8; nt++) {
                float y0 = fmaxf(fmaf(acc[mt][nt][0], sc0, sh0), 0.f);
                float y1 = fmaxf(fmaf(acc[mt][nt][1], sc0, sh0), 0.f);
                float y2 = fmaxf(fmaf(acc[mt][nt][2], sc1, sh1), 0.f);
                float y3 = fmaxf(fmaf(acc[mt][nt][3], sc1, sh1), 0.f);
                p0[nt * 2]     += y0 * wa0 + y2 * wa1;
                p0[nt * 2 + 1] += y1 * wa0 + y3 * wa1;
                p1[nt * 2]     += y0 * wb0 + y2 * wb1;
                p1[nt * 2 + 1] += y1 * wb0 + y3 * wb1;
            }
        }
        #pragma unroll
        for (int off = 4; off <= 16; off <<= 1) {
            #pragma unroll
            for (int j = 0; j < 16; j++) {
                p0[j] += __shfl_xor_sync(0xffffffffu, p0[j], off);
                p1[j] += __shfl_xor_sync(0xffffffffu, p1[j], off);
            }
        }
        if (g == 0) {
            #pragma unroll
            for (int j = 0; j < 16; j++) {
                int nl = wn * 64 + (j >> 1) * 8 + 2 * t + (j & 1);
                atomicAdd(&s_part[nl * 2],     p0[j]);
                atomicAdd(&s_part[nl * 2 + 1], p1[j]);
            }
        }
        __syncthreads();
        {
            int nl = tid >> 1, ch = tid & 1;
            atomicAdd(dout + (size_t)(b0 + nl) * 28 + w_pos * 2 + ch, s_part[tid]);
        }
    }
}

// ======================= host launch =======================
extern "C" void kernel_launch(void* const* d_in, const int* in_sizes, int n_in,
                              void* d_out, int out_size)
{
    (void)n_in;
    const float* x   = (const float*)d_in[0];
    const float* sig = (const float*)d_in[1];
    const float* w1  = (const float*)d_in[2];
    const float *w2, *w3, *w4;
    const float *g1,*b1,*m1,*v1,*g2,*b2,*m2,*v2,*g3,*b3,*m3,*v3;

    if (in_sizes[3] == 73728) {
        w2=(const float*)d_in[3];  w3=(const float*)d_in[4];  w4=(const float*)d_in[5];
        g1=(const float*)d_in[6];  b1=(const float*)d_in[7];  m1=(const float*)d_in[8];  v1=(const float*)d_in[9];
        g2=(const float*)d_in[10]; b2=(const float*)d_in[11]; m2=(const float*)d_in[12]; v2=(const float*)d_in[13];
        g3=(const float*)d_in[14]; b3=(const float*)d_in[15]; m3=(const float*)d_in[16]; v3=(const float*)d_in[17];
    } else {
        g1=(const float*)d_in[3];  b1=(const float*)d_in[4];  m1=(const float*)d_in[5];  v1=(const float*)d_in[6];
        w2=(const float*)d_in[7];
        g2=(const float*)d_in[8];  b2=(const float*)d_in[9];  m2=(const float*)d_in[10]; v2=(const float*)d_in[11];
        w3=(const float*)d_in[12];
        g3=(const float*)d_in[13]; b3=(const float*)d_in[14]; m3=(const float*)d_in[15]; v3=(const float*)d_in[16];
        w4=(const float*)d_in[17];
    }

    __half *a1, *a2, *w2h, *w3h;
    cudaGetSymbolAddress((void**)&a1, g_a1);
    cudaGetSymbolAddress((void**)&a2, g_a2);
    cudaGetSymbolAddress((void**)&w2h, g_w2);
    cudaGetSymbolAddress((void**)&w3h, g_w3);

    cudaFuncSetAttribute(conv_mma<34, 9, false>,
                         cudaFuncAttributeMaxDynamicSharedMemorySize, SMEM_TOT);
    cudaFuncSetAttribute(conv_mma<18, 18, true>,
                         cudaFuncAttributeMaxDynamicSharedMemorySize, SMEM_TOT);

    // 1) merged prep: zero d_out + all weight converts (one launch)
    prep_all_kernel<<<(294912 + 255) / 256, 256>>>((float*)d_out, out_size, w1, w2, w3);
    // 2) input -> padded fp16 CHWN
    prep_input_kernel<<<896, 256>>>(x, sig);
    // 3) conv1 via mma, pipelined over h -> a1
    conv1_mma<<<dim3(4, 112), 256>>>(g1, b1, m1, v1);
    // 4) conv2 (fp16 mma, K-chunk 64) -> a2
    conv_mma<34, 9, false><<<dim3(16, 224, 1), 256, SMEM_TOT>>>(
        a1, w2h, g2, b2, m2, v2, nullptr, a2, nullptr, 18);
    // 5) conv3 (fp16 mma, mtile = blockIdx.z) + fused conv4 -> d_out
    conv_mma<18, 18, true><<<dim3(8, 224, 2), 256, SMEM_TOT>>>(
        a2, w3h, g3, b3, m3, v3, w4, nullptr, (float*)d_out, 0);
}